// round 10
// baseline (speedup 1.0000x reference)
#include <cuda_runtime.h>
#include <cuda_fp16.h>
#include <cstdint>

// ---------------- problem-size scratch (static device globals; no allocs) ---
#define NMAX 100096
#define EMAX 1600256
#define ENMAX (NMAX + EMAX)
#define POOLB 240

__device__ int      g_not64;             // 1 if edge_index is int32
__device__ int      g_deg[NMAX];
__device__ int      g_rp[NMAX + 1];      // CSR row pointers (by SRC)
__device__ int      g_cur[NMAX];
__device__ int      g_bsum[128];
__device__ int      g_sd[ENMAX];         // dst per CSR slot (src-sorted)
__device__ float    g_h1[NMAX * 64];     // layer1 features, row-major
__device__ float    g_g1[NMAX * 64];     // layer1 output (post relu) = layer2 input
__device__ float    g_h2[NMAX * 64];     // layer2 features, row-major
__device__ float    g_g2[NMAX * 64];     // layer2 output
__device__ float    g_as1[NMAX], g_ad1[NMAX];
__device__ float    g_as2[NMAX], g_ad2[NMAX];
__device__ __half2  g_acch[NMAX * 32];   // f16x2 scatter accumulator (64 cols)
__device__ float    g_den[NMAX];         // softmax denominators (f32)
__device__ unsigned g_dmaxk[NMAX];       // per-dst max keys (monotone uint)
__device__ float    g_pool[POOLB * 64];  // pool partials

// ---------------- float<->monotone-uint key for atomicMax --------------------
__device__ __forceinline__ unsigned fkey(float f) {
    unsigned u = __float_as_uint(f);
    return (u & 0x80000000u) ? ~u : (u | 0x80000000u);
}
__device__ __forceinline__ float unkey(unsigned k) {
    unsigned u = (k & 0x80000000u) ? (k ^ 0x80000000u) : ~k;
    return __uint_as_float(u);
}

// ---------------- init ------------------------------------------------------
__global__ void k_zero(int n) {
    int i = blockIdx.x * blockDim.x + threadIdx.x;
    if (i < n) g_deg[i] = 0;
    if (i == 0) g_not64 = 0;
}

// ---------------- edge-index dtype detection --------------------------------
__global__ void k_detect(const long long* __restrict__ ei, int nq) {
    int i = blockIdx.x * blockDim.x + threadIdx.x;
    if (i < nq && ((unsigned long long)ei[i] >> 32) != 0ull) atomicOr(&g_not64, 1);
}

__device__ __forceinline__ int load_idx(const void* ei, long long pos) {
    if (g_not64) return ((const int*)ei)[pos];
    return (int)((const long long*)ei)[pos];
}

__device__ __forceinline__ int clampi(int v, int n) {
    v = v < 0 ? 0 : v;
    return v >= n ? n - 1 : v;
}

// ---------------- out-degree histogram (by SRC, incl. self loops) ------------
__global__ void k_hist(const void* __restrict__ ei, int E, int EN, int n) {
    int i = blockIdx.x * blockDim.x + threadIdx.x;
    if (i >= EN) return;
    int s = (i < E) ? clampi(load_idx(ei, i), n) : (i - E);
    atomicAdd(&g_deg[s], 1);
}

// ---------------- prefix scan -------------------------------------------------
__global__ void k_scan_block(int n) {
    __shared__ int s[1024];
    int i = blockIdx.x * 1024 + threadIdx.x;
    int v = (i < n) ? g_deg[i] : 0;
    s[threadIdx.x] = v;
    __syncthreads();
#pragma unroll
    for (int o = 1; o < 1024; o <<= 1) {
        int t = (threadIdx.x >= (unsigned)o) ? s[threadIdx.x - o] : 0;
        __syncthreads();
        s[threadIdx.x] += t;
        __syncthreads();
    }
    if (i < n) g_rp[i] = s[threadIdx.x] - v;
    if (threadIdx.x == 1023) g_bsum[blockIdx.x] = s[1023];
}

__global__ void k_scan_top(int nb) {
    __shared__ int s[128];
    int t = threadIdx.x;
    int v = (t < nb) ? g_bsum[t] : 0;
    s[t] = v;
    __syncthreads();
#pragma unroll
    for (int o = 1; o < 128; o <<= 1) {
        int tv = (t >= (unsigned)o) ? s[t - o] : 0;
        __syncthreads();
        s[t] += tv;
        __syncthreads();
    }
    if (t < nb) g_bsum[t] = s[t] - v;
}

__global__ void k_scan_add(int n, int total) {
    int i = blockIdx.x * blockDim.x + threadIdx.x;
    if (i < n) {
        int v = g_rp[i] + g_bsum[i >> 10];
        g_rp[i] = v;
        g_cur[i] = v;
    }
    if (i == 0) g_rp[n] = total;
}

// ---------------- scatter edges into src-CSR order (store dst) --------------
__global__ void k_scatter(const void* __restrict__ ei, int E, int EN, int n) {
    int i = blockIdx.x * blockDim.x + threadIdx.x;
    if (i >= EN) return;
    int s, d;
    if (i < E) {
        s = clampi(load_idx(ei, i), n);
        d = clampi(load_idx(ei, (long long)E + i), n);
    } else { s = i - E; d = s; }
    int pos = atomicAdd(&g_cur[s], 1);
    if (pos >= 0 && pos < ENMAX) g_sd[pos] = d;
}

// ---------------- GEMM + attention scalars ----------------------------------
// 256 threads, 8 warps, 4 node-rows per warp; W staged in 64-k halves (16KB)
// to keep smem <= 33KB -> 6 blocks/SM (75% occ).
template <int FIN>
__global__ void __launch_bounds__(256)
k_gemm(const float* __restrict__ X, const float* __restrict__ Wg,
       const float* __restrict__ att_s, const float* __restrict__ att_d,
       float* __restrict__ H, float* __restrict__ AS, float* __restrict__ AD,
       int n) {
    __shared__ float2 Wp[64 * 32];           // one 64-k half of W
    __shared__ float atts[64], attd[64];
    __shared__ __align__(16) float xs[8][4][FIN];

    int tid = threadIdx.x;
    int warp = tid >> 5, lane = tid & 31;
    if (tid < 64) { atts[tid] = att_s[tid]; attd[tid] = att_d[tid]; }

    int base = (blockIdx.x * 8 + warp) * 4;
    int nrows = n - base;
    if (nrows < 0) nrows = 0;
    if (nrows > 4) nrows = 4;

    for (int r = 0; r < nrows; r++) {
        const float* xp = X + (size_t)(base + r) * FIN;
#pragma unroll
        for (int k = lane; k < FIN; k += 32) xs[warp][r][k] = xp[k];
    }

    float acc[4][2];
#pragma unroll
    for (int r = 0; r < 4; r++) { acc[r][0] = 0.f; acc[r][1] = 0.f; }

#pragma unroll
    for (int ph = 0; ph < FIN / 64; ph++) {
        __syncthreads();
        for (int i = tid; i < 64 * 32; i += 256) {
            int k = i >> 5, c = i & 31;
            int kg = ph * 64 + k;
            Wp[i] = make_float2(Wg[kg * 64 + c], Wg[kg * 64 + c + 32]);
        }
        __syncthreads();

#pragma unroll 8
        for (int k4 = 0; k4 < 64; k4 += 4) {
            float4 xv[4];
#pragma unroll
            for (int r = 0; r < 4; r++)
                xv[r] = *(const float4*)&xs[warp][r][ph * 64 + k4];
#pragma unroll
            for (int kk = 0; kk < 4; kk++) {
                float2 w = Wp[(k4 + kk) * 32 + lane];
#pragma unroll
                for (int r = 0; r < 4; r++) {
                    float xr = (kk == 0) ? xv[r].x : (kk == 1) ? xv[r].y
                             : (kk == 2) ? xv[r].z : xv[r].w;
                    acc[r][0] += xr * w.x;
                    acc[r][1] += xr * w.y;
                }
            }
        }
    }

#pragma unroll
    for (int r = 0; r < 4; r++) {
        if (r >= nrows) break;
        float v0 = acc[r][0], v1 = acc[r][1];
        size_t o = (size_t)(base + r) * 64;
        H[o + lane] = v0;
        H[o + 32 + lane] = v1;
        float ps = v0 * atts[lane] + v1 * atts[lane + 32];
        float pd = v0 * attd[lane] + v1 * attd[lane + 32];
#pragma unroll
        for (int ofs = 16; ofs; ofs >>= 1) {
            ps += __shfl_xor_sync(0xffffffffu, ps, ofs);
            pd += __shfl_xor_sync(0xffffffffu, pd, ofs);
        }
        if (lane == 0) { AS[base + r] = ps; AD[base + r] = pd; }
    }
}

// ---------------- zero accumulators + per-dst max keys -----------------------
__global__ void k_zeroacc(int n) {
    int total = n * 32;   // half2 count = n*32 uints
    for (int i = blockIdx.x * blockDim.x + threadIdx.x; i < total;
         i += gridDim.x * blockDim.x) {
        ((unsigned*)g_acch)[i] = 0u;
        if (i < n) { g_den[i] = 0.f; g_dmaxk[i] = 0u; }   // key 0 == -inf-ish
    }
}

// ---------------- per-dst max of leaky_relu(e) (warp per SRC) ----------------
__global__ void __launch_bounds__(256)
k_emax(const float* __restrict__ AS, const float* __restrict__ AD, int n) {
    int src = (blockIdx.x * blockDim.x + threadIdx.x) >> 5;
    int lane = threadIdx.x & 31;
    if (src >= n) return;
    float as_v = AS[src];
    int beg = g_rp[src], end = g_rp[src + 1];
    for (int j = beg + lane; j < end; j += 32) {
        int d = g_sd[j];
        float e = as_v + AD[d];
        e = (e > 0.f) ? e : 0.2f * e;
        atomicMax(&g_dmaxk[d], fkey(e));
    }
}

// ---------------- scatter aggregation: f16x2 atomics, half-warp per edge -----
__device__ __forceinline__ void red_h2(__half2* p, __half2 v) {
    unsigned u = *reinterpret_cast<unsigned*>(&v);
    asm volatile("red.global.add.noftz.f16x2 [%0], %1;"
                 :: "l"(p), "r"(u) : "memory");
}

__global__ void __launch_bounds__(256)
k_scatagg(const float* __restrict__ H, const float* __restrict__ AS,
          const float* __restrict__ AD, int n) {
    int src = (blockIdx.x * blockDim.x + threadIdx.x) >> 5;
    int lane = threadIdx.x & 31;
    if (src >= n) return;

    int q = lane & 15;          // column group 0..15 (4 floats each)
    int half = lane >> 4;       // 0: even edge, 1: odd edge
    float4 hv = *(const float4*)(H + (size_t)src * 64 + q * 4);
    float as_v = AS[src];
    int beg = g_rp[src], end = g_rp[src + 1];

    int j = beg;
    for (; j + 1 < end; j += 2) {
        int d = g_sd[j + half];
        float e = as_v + AD[d];
        e = (e > 0.f) ? e : 0.2f * e;
        float w = __expf(e - unkey(g_dmaxk[d]));     // w <= 1
        __half2* ap = g_acch + (size_t)d * 32 + q * 2;
        red_h2(ap,     __floats2half2_rn(w * hv.x, w * hv.y));
        red_h2(ap + 1, __floats2half2_rn(w * hv.z, w * hv.w));
        if (q == 0) atomicAdd(&g_den[d], w);
    }
    if (j < end && half == 0) {
        int d = g_sd[j];
        float e = as_v + AD[d];
        e = (e > 0.f) ? e : 0.2f * e;
        float w = __expf(e - unkey(g_dmaxk[d]));
        __half2* ap = g_acch + (size_t)d * 32 + q * 2;
        red_h2(ap,     __floats2half2_rn(w * hv.x, w * hv.y));
        red_h2(ap + 1, __floats2half2_rn(w * hv.z, w * hv.w));
        if (q == 0) atomicAdd(&g_den[d], w);
    }
}

// ---------------- normalize + bias (+relu) -----------------------------------
__global__ void k_norm(const float* __restrict__ bias, float* __restrict__ OUT,
                       int n, int do_relu) {
    int total = n * 32;   // half2 units
    for (int i = blockIdx.x * blockDim.x + threadIdx.x; i < total;
         i += gridDim.x * blockDim.x) {
        int node = i >> 5, c = i & 31;
        float2 v = __half22float2(g_acch[i]);
        float inv = 1.f / (g_den[node] + 1e-16f);
        float o0 = v.x * inv + bias[2 * c];
        float o1 = v.y * inv + bias[2 * c + 1];
        if (do_relu) { o0 = fmaxf(o0, 0.f); o1 = fmaxf(o1, 0.f); }
        ((float2*)OUT)[(size_t)node * 32 + c] = make_float2(o0, o1);
    }
}

// ---------------- global mean pool (atomic-free, 2 stages) -------------------
__global__ void k_pool_a(const float* __restrict__ G, int n) {
    __shared__ float sm[256];
    int col = threadIdx.x & 63;
    int rg = threadIdx.x >> 6;
    float acc = 0.f;
    for (int r = blockIdx.x * 4 + rg; r < n; r += gridDim.x * 4)
        acc += G[(size_t)r * 64 + col];
    sm[threadIdx.x] = acc;
    __syncthreads();
    if (rg == 0)
        g_pool[blockIdx.x * 64 + col] =
            sm[col] + sm[64 + col] + sm[128 + col] + sm[192 + col];
}

__global__ void k_pool_b(float* __restrict__ out, int n) {
    int col = threadIdx.x;
    float acc = 0.f;
    for (int b = 0; b < POOLB; b++) acc += g_pool[b * 64 + col];
    out[col] = acc * (1.0f / (float)n);
}

// ---------------- launch ----------------------------------------------------
extern "C" void kernel_launch(void* const* d_in, const int* in_sizes, int n_in,
                              void* d_out, int out_size) {
    const float* x   = (const float*)d_in[0];
    const void*  ei  = d_in[1];
    const float* W1  = (const float*)d_in[3];
    const float* as1 = (const float*)d_in[4];
    const float* ad1 = (const float*)d_in[5];
    const float* b1  = (const float*)d_in[6];
    const float* W2  = (const float*)d_in[7];
    const float* as2 = (const float*)d_in[8];
    const float* ad2 = (const float*)d_in[9];
    const float* b2  = (const float*)d_in[10];
    float* out = (float*)d_out;

    int n  = in_sizes[0] / 128;   // N nodes
    int E  = in_sizes[1] / 2;     // edges
    int EN = E + n;               // edges + self loops

    int gemmBlocks = (n + 31) / 32;
    int aggBlocks  = (n + 7) / 8;

    k_zero<<<(n + 255) / 256, 256>>>(n);                               // 0
    int nq = E < 2048 ? E : 2048;
    k_detect<<<(nq + 255) / 256, 256>>>((const long long*)ei, nq);     // 1
    k_hist<<<(EN + 255) / 256, 256>>>(ei, E, EN, n);                   // 2
    // Slot 3 (profiled): K-split gemm128 — verify occupancy fix.
    k_gemm<128><<<gemmBlocks, 256>>>(x, W1, as1, ad1,
                                     g_h1, g_as1, g_ad1, n);           // 3 <- profiled
    int nb = (n + 1023) / 1024;
    k_scan_block<<<nb, 1024>>>(n);
    k_scan_top<<<1, 128>>>(nb);
    k_scan_add<<<(n + 255) / 256, 256>>>(n, EN);
    k_scatter<<<(EN + 255) / 256, 256>>>(ei, E, EN, n);

    // --- layer 1: max pass + f16x2 scatter aggregation + normalize(relu) ---
    k_zeroacc<<<480, 256>>>(n);
    k_emax<<<aggBlocks, 256>>>(g_as1, g_ad1, n);
    k_scatagg<<<aggBlocks, 256>>>(g_h1, g_as1, g_ad1, n);
    k_norm<<<480, 256>>>(b1, g_g1, n, 1);

    // --- layer 2 ---
    k_gemm<64><<<gemmBlocks, 256>>>(g_g1, W2, as2, ad2, g_h2, g_as2, g_ad2, n);
    k_zeroacc<<<480, 256>>>(n);
    k_emax<<<aggBlocks, 256>>>(g_as2, g_ad2, n);
    k_scatagg<<<aggBlocks, 256>>>(g_h2, g_as2, g_ad2, n);
    k_norm<<<480, 256>>>(b2, g_g2, n, 0);

    // --- global mean pool (atomic-free) ---
    k_pool_a<<<POOLB, 256>>>(g_g2, n);
    k_pool_b<<<1, 64>>>(out, n);
}

// round 11
// speedup vs baseline: 1.8176x; 1.8176x over previous
#include <cuda_runtime.h>
#include <cuda_fp16.h>
#include <cstdint>

// ---------------- problem-size scratch (static device globals; no allocs) ---
#define NMAX 100096
#define EMAX 1600256
#define ENMAX (NMAX + EMAX)
#define POOLB 592

__device__ int    g_not64;               // 1 if edge_index is int32
__device__ int    g_deg[NMAX];
__device__ int    g_rp[NMAX + 1];        // CSR row pointers (by SRC)
__device__ int    g_cur[NMAX];
__device__ int    g_bsum[128];
__device__ int    g_sd[ENMAX];           // dst per CSR slot (src-sorted)
__device__ float  g_w[ENMAX];            // layer2 edge weights
__device__ float  g_h1[NMAX * 64];       // layer1 features, row-major
__device__ float  g_h2[NMAX * 64];       // layer2 features, row-major
__device__ float  g_as1[NMAX], g_ad1[NMAX];
__device__ float  g_as2[NMAX], g_ad2[NMAX];
__device__ float  g_acc[NMAX * 64];      // layer1 scatter accumulator
__device__ float  g_den[NMAX];           // denominators (layer1, then reused layer2)
__device__ float  g_pool[POOLB * 64];    // pool partials

// ---------------- init ------------------------------------------------------
__global__ void k_zero(int n) {
    int i = blockIdx.x * blockDim.x + threadIdx.x;
    if (i < n) g_deg[i] = 0;
    if (i == 0) g_not64 = 0;
}

// ---------------- edge-index dtype detection --------------------------------
__global__ void k_detect(const long long* __restrict__ ei, int nq) {
    int i = blockIdx.x * blockDim.x + threadIdx.x;
    if (i < nq && ((unsigned long long)ei[i] >> 32) != 0ull) atomicOr(&g_not64, 1);
}

__device__ __forceinline__ int load_idx(const void* ei, long long pos) {
    if (g_not64) return ((const int*)ei)[pos];
    return (int)((const long long*)ei)[pos];
}

__device__ __forceinline__ int clampi(int v, int n) {
    v = v < 0 ? 0 : v;
    return v >= n ? n - 1 : v;
}

// ---------------- out-degree histogram (by SRC, incl. self loops) ------------
__global__ void k_hist(const void* __restrict__ ei, int E, int EN, int n) {
    int i = blockIdx.x * blockDim.x + threadIdx.x;
    if (i >= EN) return;
    int s = (i < E) ? clampi(load_idx(ei, i), n) : (i - E);
    atomicAdd(&g_deg[s], 1);
}

// ---------------- prefix scan -------------------------------------------------
__global__ void k_scan_block(int n) {
    __shared__ int s[1024];
    int i = blockIdx.x * 1024 + threadIdx.x;
    int v = (i < n) ? g_deg[i] : 0;
    s[threadIdx.x] = v;
    __syncthreads();
#pragma unroll
    for (int o = 1; o < 1024; o <<= 1) {
        int t = (threadIdx.x >= (unsigned)o) ? s[threadIdx.x - o] : 0;
        __syncthreads();
        s[threadIdx.x] += t;
        __syncthreads();
    }
    if (i < n) g_rp[i] = s[threadIdx.x] - v;
    if (threadIdx.x == 1023) g_bsum[blockIdx.x] = s[1023];
}

__global__ void k_scan_top(int nb) {
    __shared__ int s[128];
    int t = threadIdx.x;
    int v = (t < nb) ? g_bsum[t] : 0;
    s[t] = v;
    __syncthreads();
#pragma unroll
    for (int o = 1; o < 128; o <<= 1) {
        int tv = (t >= (unsigned)o) ? s[t - o] : 0;
        __syncthreads();
        s[t] += tv;
        __syncthreads();
    }
    if (t < nb) g_bsum[t] = s[t] - v;
}

__global__ void k_scan_add(int n, int total) {
    int i = blockIdx.x * blockDim.x + threadIdx.x;
    if (i < n) {
        int v = g_rp[i] + g_bsum[i >> 10];
        g_rp[i] = v;
        g_cur[i] = v;
    }
    if (i == 0) g_rp[n] = total;
}

// ---------------- scatter edges into src-CSR order (store dst) --------------
__global__ void k_scatter(const void* __restrict__ ei, int E, int EN, int n) {
    int i = blockIdx.x * blockDim.x + threadIdx.x;
    if (i >= EN) return;
    int s, d;
    if (i < E) {
        s = clampi(load_idx(ei, i), n);
        d = clampi(load_idx(ei, (long long)E + i), n);
    } else { s = i - E; d = s; }
    int pos = atomicAdd(&g_cur[s], 1);
    if (pos >= 0 && pos < ENMAX) g_sd[pos] = d;
}

// ---------------- GEMM1 (128->64) + attention scalars ------------------------
// 256 threads, 8 warps, 4 node-rows per warp; W staged in 64-k halves.
__global__ void __launch_bounds__(256)
k_gemm128(const float* __restrict__ X, const float* __restrict__ Wg,
          const float* __restrict__ att_s, const float* __restrict__ att_d,
          float* __restrict__ H, float* __restrict__ AS, float* __restrict__ AD,
          int n) {
    __shared__ float2 Wp[64 * 32];
    __shared__ float atts[64], attd[64];
    __shared__ __align__(16) float xs[8][4][128];

    int tid = threadIdx.x;
    int warp = tid >> 5, lane = tid & 31;
    if (tid < 64) { atts[tid] = att_s[tid]; attd[tid] = att_d[tid]; }

    int base = (blockIdx.x * 8 + warp) * 4;
    int nrows = n - base;
    if (nrows < 0) nrows = 0;
    if (nrows > 4) nrows = 4;

    for (int r = 0; r < nrows; r++) {
        const float* xp = X + (size_t)(base + r) * 128;
#pragma unroll
        for (int k = lane; k < 128; k += 32) xs[warp][r][k] = xp[k];
    }

    float acc[4][2];
#pragma unroll
    for (int r = 0; r < 4; r++) { acc[r][0] = 0.f; acc[r][1] = 0.f; }

#pragma unroll
    for (int ph = 0; ph < 2; ph++) {
        __syncthreads();
        for (int i = tid; i < 64 * 32; i += 256) {
            int k = i >> 5, c = i & 31;
            int kg = ph * 64 + k;
            Wp[i] = make_float2(Wg[kg * 64 + c], Wg[kg * 64 + c + 32]);
        }
        __syncthreads();

#pragma unroll 8
        for (int k4 = 0; k4 < 64; k4 += 4) {
            float4 xv[4];
#pragma unroll
            for (int r = 0; r < 4; r++)
                xv[r] = *(const float4*)&xs[warp][r][ph * 64 + k4];
#pragma unroll
            for (int kk = 0; kk < 4; kk++) {
                float2 w = Wp[(k4 + kk) * 32 + lane];
#pragma unroll
                for (int r = 0; r < 4; r++) {
                    float xr = (kk == 0) ? xv[r].x : (kk == 1) ? xv[r].y
                             : (kk == 2) ? xv[r].z : xv[r].w;
                    acc[r][0] += xr * w.x;
                    acc[r][1] += xr * w.y;
                }
            }
        }
    }

#pragma unroll
    for (int r = 0; r < 4; r++) {
        if (r >= nrows) break;
        float v0 = acc[r][0], v1 = acc[r][1];
        size_t o = (size_t)(base + r) * 64;
        H[o + lane] = v0;
        H[o + 32 + lane] = v1;
        float ps = v0 * atts[lane] + v1 * atts[lane + 32];
        float pd = v0 * attd[lane] + v1 * attd[lane + 32];
#pragma unroll
        for (int ofs = 16; ofs; ofs >>= 1) {
            ps += __shfl_xor_sync(0xffffffffu, ps, ofs);
            pd += __shfl_xor_sync(0xffffffffu, pd, ofs);
        }
        if (lane == 0) { AS[base + r] = ps; AD[base + r] = pd; }
    }
}

// ---------------- zero layer-1 accumulators ----------------------------------
__global__ void k_zeroacc(int n) {
    int total = n * 16;   // float4 count
    float4 z = make_float4(0.f, 0.f, 0.f, 0.f);
    for (int i = blockIdx.x * blockDim.x + threadIdx.x; i < total;
         i += gridDim.x * blockDim.x) {
        ((float4*)g_acc)[i] = z;
        if (i < n) g_den[i] = 0.f;
    }
}

// ---------------- layer-1 scatter aggregation (f32, R8 form) -----------------
__device__ __forceinline__ void red_v4(float* p, float a, float b, float c, float d) {
    asm volatile("red.global.add.v4.f32 [%0], {%1, %2, %3, %4};"
                 :: "l"(p), "f"(a), "f"(b), "f"(c), "f"(d) : "memory");
}

__global__ void __launch_bounds__(256)
k_scatagg(const float* __restrict__ H, const float* __restrict__ AS,
          const float* __restrict__ AD, int n) {
    int src = (blockIdx.x * blockDim.x + threadIdx.x) >> 5;
    int lane = threadIdx.x & 31;
    if (src >= n) return;

    int q = lane & 15;
    int half = lane >> 4;
    float4 hv = *(const float4*)(H + (size_t)src * 64 + q * 4);
    float as_v = AS[src];
    int beg = g_rp[src], end = g_rp[src + 1];

    int j = beg;
    for (; j + 1 < end; j += 2) {
        int d = g_sd[j + half];
        float e = as_v + AD[d];
        e = (e > 0.f) ? e : 0.2f * e;
        float w = __expf(e);
        float* ap = g_acc + (size_t)d * 64 + q * 4;
        red_v4(ap, w * hv.x, w * hv.y, w * hv.z, w * hv.w);
        if (q == 0) atomicAdd(&g_den[d], w);
    }
    if (j < end && half == 0) {
        int d = g_sd[j];
        float e = as_v + AD[d];
        e = (e > 0.f) ? e : 0.2f * e;
        float w = __expf(e);
        float* ap = g_acc + (size_t)d * 64 + q * 4;
        red_v4(ap, w * hv.x, w * hv.y, w * hv.z, w * hv.w);
        if (q == 0) atomicAdd(&g_den[d], w);
    }
}

// ---------------- GEMM2 (64->64) with fused normalize+bias+relu on input -----
// x_row = relu(g_acc_row / (g_den+eps) + b1); each row read exactly once.
__global__ void __launch_bounds__(256)
k_gemm64f(const float* __restrict__ Wg, const float* __restrict__ b1,
          const float* __restrict__ att_s, const float* __restrict__ att_d,
          float* __restrict__ H, float* __restrict__ AS, float* __restrict__ AD,
          int n) {
    __shared__ float2 Wp[64 * 32];
    __shared__ float atts[64], attd[64], bs[64];
    __shared__ __align__(16) float xs[8][4][64];

    int tid = threadIdx.x;
    int warp = tid >> 5, lane = tid & 31;
    if (tid < 64) { atts[tid] = att_s[tid]; attd[tid] = att_d[tid]; bs[tid] = b1[tid]; }
    for (int i = tid; i < 64 * 32; i += 256) {
        int k = i >> 5, c = i & 31;
        Wp[i] = make_float2(Wg[k * 64 + c], Wg[k * 64 + c + 32]);
    }
    __syncthreads();

    int base = (blockIdx.x * 8 + warp) * 4;
    int nrows = n - base;
    if (nrows < 0) nrows = 0;
    if (nrows > 4) nrows = 4;

    for (int r = 0; r < nrows; r++) {
        int row = base + r;
        float inv = 1.f / (g_den[row] + 1e-16f);
        const float* xp = g_acc + (size_t)row * 64;
#pragma unroll
        for (int k = lane; k < 64; k += 32)
            xs[warp][r][k] = fmaxf(xp[k] * inv + bs[k], 0.f);
    }
    __syncwarp();

    float acc[4][2];
#pragma unroll
    for (int r = 0; r < 4; r++) { acc[r][0] = 0.f; acc[r][1] = 0.f; }

#pragma unroll 8
    for (int k4 = 0; k4 < 64; k4 += 4) {
        float4 xv[4];
#pragma unroll
        for (int r = 0; r < 4; r++)
            xv[r] = *(const float4*)&xs[warp][r][k4];
#pragma unroll
        for (int kk = 0; kk < 4; kk++) {
            float2 w = Wp[(k4 + kk) * 32 + lane];
#pragma unroll
            for (int r = 0; r < 4; r++) {
                float xr = (kk == 0) ? xv[r].x : (kk == 1) ? xv[r].y
                         : (kk == 2) ? xv[r].z : xv[r].w;
                acc[r][0] += xr * w.x;
                acc[r][1] += xr * w.y;
            }
        }
    }

#pragma unroll
    for (int r = 0; r < 4; r++) {
        if (r >= nrows) break;
        float v0 = acc[r][0], v1 = acc[r][1];
        size_t o = (size_t)(base + r) * 64;
        H[o + lane] = v0;
        H[o + 32 + lane] = v1;
        float ps = v0 * atts[lane] + v1 * atts[lane + 32];
        float pd = v0 * attd[lane] + v1 * attd[lane + 32];
#pragma unroll
        for (int ofs = 16; ofs; ofs >>= 1) {
            ps += __shfl_xor_sync(0xffffffffu, ps, ofs);
            pd += __shfl_xor_sync(0xffffffffu, pd, ofs);
        }
        if (lane == 0) { AS[base + r] = ps; AD[base + r] = pd; }
    }
}

// ---------------- zero den2 ---------------------------------------------------
__global__ void k_zeroden(int n) {
    int i = blockIdx.x * blockDim.x + threadIdx.x;
    if (i < n) g_den[i] = 0.f;
}

// ---------------- layer-2 denominators + edge weights (warp per SRC) ---------
__global__ void __launch_bounds__(256)
k_den2(const float* __restrict__ AS, const float* __restrict__ AD, int n) {
    int src = (blockIdx.x * blockDim.x + threadIdx.x) >> 5;
    int lane = threadIdx.x & 31;
    if (src >= n) return;
    float as_v = AS[src];
    int beg = g_rp[src], end = g_rp[src + 1];
    for (int j = beg + lane; j < end; j += 32) {
        int d = g_sd[j];
        float e = as_v + AD[d];
        e = (e > 0.f) ? e : 0.2f * e;
        float w = __expf(e);
        g_w[j] = w;
        atomicAdd(&g_den[d], w);
    }
}

// ---------------- layer-2 collapsed aggregation+pool: warp per SRC -----------
// c_src = sum_{out-edges} w_j/(den2[d_j]+eps); pool += c_src * h2[src].
__global__ void __launch_bounds__(256)
k_coefpool(const float* __restrict__ H2, int n) {
    __shared__ float sm[8][64];
    int warp = threadIdx.x >> 5, lane = threadIdx.x & 31;
    int gw = blockIdx.x * 8 + warp;
    int stride = gridDim.x * 8;

    float acc0 = 0.f, acc1 = 0.f;
    for (int src = gw; src < n; src += stride) {
        int beg = g_rp[src], end = g_rp[src + 1];
        float a = 0.f;
        for (int j = beg + lane; j < end; j += 32)
            a += g_w[j] / (g_den[g_sd[j]] + 1e-16f);
#pragma unroll
        for (int o = 16; o; o >>= 1) a += __shfl_xor_sync(0xffffffffu, a, o);
        const float* hp = H2 + (size_t)src * 64;
        acc0 += a * hp[lane];
        acc1 += a * hp[lane + 32];
    }
    sm[warp][lane] = acc0;
    sm[warp][lane + 32] = acc1;
    __syncthreads();
    if (threadIdx.x < 64) {
        float v = 0.f;
#pragma unroll
        for (int w = 0; w < 8; w++) v += sm[w][threadIdx.x];
        g_pool[blockIdx.x * 64 + threadIdx.x] = v;
    }
}

// ---------------- final reduce + bias ----------------------------------------
__global__ void k_pool_b(const float* __restrict__ b2, float* __restrict__ out,
                         int n) {
    int col = threadIdx.x;   // 64 threads
    float acc = 0.f;
    for (int b = 0; b < POOLB; b++) acc += g_pool[b * 64 + col];
    out[col] = acc * (1.0f / (float)n) + b2[col];
}

// ---------------- launch ----------------------------------------------------
extern "C" void kernel_launch(void* const* d_in, const int* in_sizes, int n_in,
                              void* d_out, int out_size) {
    const float* x   = (const float*)d_in[0];
    const void*  ei  = d_in[1];
    const float* W1  = (const float*)d_in[3];
    const float* as1 = (const float*)d_in[4];
    const float* ad1 = (const float*)d_in[5];
    const float* b1  = (const float*)d_in[6];
    const float* W2  = (const float*)d_in[7];
    const float* as2 = (const float*)d_in[8];
    const float* ad2 = (const float*)d_in[9];
    const float* b2  = (const float*)d_in[10];
    float* out = (float*)d_out;

    int n  = in_sizes[0] / 128;   // N nodes
    int E  = in_sizes[1] / 2;     // edges
    int EN = E + n;               // edges + self loops

    int gemmBlocks = (n + 31) / 32;
    int aggBlocks  = (n + 7) / 8;

    k_zero<<<(n + 255) / 256, 256>>>(n);                               // 0
    int nq = E < 2048 ? E : 2048;
    k_detect<<<(nq + 255) / 256, 256>>>((const long long*)ei, nq);     // 1
    k_hist<<<(EN + 255) / 256, 256>>>(ei, E, EN, n);                   // 2
    k_gemm128<<<gemmBlocks, 256>>>(x, W1, as1, ad1,
                                   g_h1, g_as1, g_ad1, n);             // 3 <- profiled
    int nb = (n + 1023) / 1024;
    k_scan_block<<<nb, 1024>>>(n);
    k_scan_top<<<1, 128>>>(nb);
    k_scan_add<<<(n + 255) / 256, 256>>>(n, EN);
    k_scatter<<<(EN + 255) / 256, 256>>>(ei, E, EN, n);

    // --- layer 1: f32 scatter aggregation ---
    k_zeroacc<<<480, 256>>>(n);
    k_scatagg<<<aggBlocks, 256>>>(g_h1, g_as1, g_ad1, n);

    // --- layer 2: gemm with fused normalize(relu); collapsed aggregation ---
    k_gemm64f<<<gemmBlocks, 256>>>(W2, b1, as2, ad2, g_h2, g_as2, g_ad2, n);
    k_zeroden<<<(n + 255) / 256, 256>>>(n);
    k_den2<<<aggBlocks, 256>>>(g_as2, g_ad2, n);
    k_coefpool<<<POOLB, 256>>>(g_h2, n);
    k_pool_b<<<1, 64>>>(b2, out, n);
}

// round 12
// speedup vs baseline: 1.8323x; 1.0081x over previous
#include <cuda_runtime.h>
#include <cuda_fp16.h>
#include <cstdint>

// ---------------- problem-size scratch (static device globals; no allocs) ---
#define NMAX 100096
#define EMAX 1600256
#define ENMAX (NMAX + EMAX)
#define POOLB 592

__device__ int    g_not64;               // 1 if edge_index is int32
__device__ int    g_deg[NMAX];
__device__ int    g_rp[NMAX + 1];        // CSR row pointers (by SRC)
__device__ int    g_cur[NMAX];
__device__ int    g_bsum[128];
__device__ int    g_sd[ENMAX];           // dst per CSR slot (src-sorted)
__device__ float  g_w[ENMAX];            // layer2 edge weights
__device__ float  g_h1[NMAX * 64];       // layer1 features, row-major
__device__ float  g_h2[NMAX * 64];       // layer2 features, row-major
__device__ float  g_as1[NMAX], g_ad1[NMAX];
__device__ float  g_as2[NMAX], g_ad2[NMAX];
__device__ float  g_acc[NMAX * 64];      // layer1 scatter accumulator
__device__ float  g_den[NMAX];           // denominators (layer1, then reused layer2)
__device__ float  g_pool[POOLB * 64];    // pool partials

// ---------------- init ------------------------------------------------------
__global__ void k_zero(int n) {
    int i = blockIdx.x * blockDim.x + threadIdx.x;
    if (i < n) g_deg[i] = 0;
    if (i == 0) g_not64 = 0;
}

// ---------------- edge-index dtype detection --------------------------------
__global__ void k_detect(const long long* __restrict__ ei, int nq) {
    int i = blockIdx.x * blockDim.x + threadIdx.x;
    if (i < nq && ((unsigned long long)ei[i] >> 32) != 0ull) atomicOr(&g_not64, 1);
}

__device__ __forceinline__ int load_idx(const void* ei, long long pos) {
    if (g_not64) return ((const int*)ei)[pos];
    return (int)((const long long*)ei)[pos];
}

__device__ __forceinline__ int clampi(int v, int n) {
    v = v < 0 ? 0 : v;
    return v >= n ? n - 1 : v;
}

// ---------------- out-degree histogram (by SRC, incl. self loops) ------------
__global__ void k_hist(const void* __restrict__ ei, int E, int EN, int n) {
    int i = blockIdx.x * blockDim.x + threadIdx.x;
    if (i >= EN) return;
    int s = (i < E) ? clampi(load_idx(ei, i), n) : (i - E);
    atomicAdd(&g_deg[s], 1);
}

// ---------------- prefix scan -------------------------------------------------
__global__ void k_scan_block(int n) {
    __shared__ int s[1024];
    int i = blockIdx.x * 1024 + threadIdx.x;
    int v = (i < n) ? g_deg[i] : 0;
    s[threadIdx.x] = v;
    __syncthreads();
#pragma unroll
    for (int o = 1; o < 1024; o <<= 1) {
        int t = (threadIdx.x >= (unsigned)o) ? s[threadIdx.x - o] : 0;
        __syncthreads();
        s[threadIdx.x] += t;
        __syncthreads();
    }
    if (i < n) g_rp[i] = s[threadIdx.x] - v;
    if (threadIdx.x == 1023) g_bsum[blockIdx.x] = s[1023];
}

__global__ void k_scan_top(int nb) {
    __shared__ int s[128];
    int t = threadIdx.x;
    int v = (t < nb) ? g_bsum[t] : 0;
    s[t] = v;
    __syncthreads();
#pragma unroll
    for (int o = 1; o < 128; o <<= 1) {
        int tv = (t >= (unsigned)o) ? s[t - o] : 0;
        __syncthreads();
        s[t] += tv;
        __syncthreads();
    }
    if (t < nb) g_bsum[t] = s[t] - v;
}

__global__ void k_scan_add(int n, int total) {
    int i = blockIdx.x * blockDim.x + threadIdx.x;
    if (i < n) {
        int v = g_rp[i] + g_bsum[i >> 10];
        g_rp[i] = v;
        g_cur[i] = v;
    }
    if (i == 0) g_rp[n] = total;
}

// ---------------- scatter edges into src-CSR order (store dst) --------------
__global__ void k_scatter(const void* __restrict__ ei, int E, int EN, int n) {
    int i = blockIdx.x * blockDim.x + threadIdx.x;
    if (i >= EN) return;
    int s, d;
    if (i < E) {
        s = clampi(load_idx(ei, i), n);
        d = clampi(load_idx(ei, (long long)E + i), n);
    } else { s = i - E; d = s; }
    int pos = atomicAdd(&g_cur[s], 1);
    if (pos >= 0 && pos < ENMAX) g_sd[pos] = d;
}

// ---------------- SGEMM1 (128->64): 64x64 tile, 4x4 micro-tiles ---------------
// i = tid>>4 (row quad), j = tid&15 (col quad). x tile stored k-major with
// 16B-granule XOR swizzle; per k per warp: ~4 smem wavefronts for 16 warp-FFMA.
__global__ void __launch_bounds__(256)
k_sgemm128(const float* __restrict__ X, const float* __restrict__ Wg,
           const float* __restrict__ att_s, const float* __restrict__ att_d,
           float* __restrict__ H, float* __restrict__ AS, float* __restrict__ AD,
           int n) {
    __shared__ float xs[64 * 64];   // [k][row] swizzled
    __shared__ float ws[64 * 64];   // [k][col]
    __shared__ float atts[64], attd[64];
    __shared__ float asd[128];

    int tid = threadIdx.x;
    int i = tid >> 4, j = tid & 15;
    int base = blockIdx.x * 64;

    if (tid < 64) { atts[tid] = att_s[tid]; attd[tid] = att_d[tid]; }
    if (tid < 128) asd[tid] = 0.f;

    float acc[4][4];
#pragma unroll
    for (int r = 0; r < 4; r++)
#pragma unroll
        for (int c = 0; c < 4; c++) acc[r][c] = 0.f;

#pragma unroll
    for (int ph = 0; ph < 2; ph++) {
        __syncthreads();
        // X tile: rows base..base+63, k-chunk ph*64..+63, transposed+swizzled
#pragma unroll
        for (int t = tid; t < 1024; t += 256) {
            int row = t >> 4, c4 = t & 15;
            int rc = base + row < n ? base + row : n - 1;
            float4 v = *(const float4*)(X + (size_t)rc * 128 + ph * 64 + c4 * 4);
            int g0 = row >> 2, r3 = row & 3;
#pragma unroll
            for (int s = 0; s < 4; s++) {
                int k = c4 * 4 + s;
                float val = (s == 0) ? v.x : (s == 1) ? v.y : (s == 2) ? v.z : v.w;
                xs[k * 64 + ((g0 ^ (k & 15)) << 2) + r3] = val;
            }
        }
        // W tile
#pragma unroll
        for (int t = tid; t < 1024; t += 256) {
            int k = t >> 4, c4 = t & 15;
            *(float4*)(ws + k * 64 + c4 * 4) =
                *(const float4*)(Wg + (size_t)(ph * 64 + k) * 64 + c4 * 4);
        }
        __syncthreads();

#pragma unroll 4
        for (int k = 0; k < 64; k++) {
            float4 a = *(const float4*)(xs + k * 64 + ((i ^ (k & 15)) << 2));
            float4 b = *(const float4*)(ws + k * 64 + j * 4);
            acc[0][0] += a.x * b.x; acc[0][1] += a.x * b.y;
            acc[0][2] += a.x * b.z; acc[0][3] += a.x * b.w;
            acc[1][0] += a.y * b.x; acc[1][1] += a.y * b.y;
            acc[1][2] += a.y * b.z; acc[1][3] += a.y * b.w;
            acc[2][0] += a.z * b.x; acc[2][1] += a.z * b.y;
            acc[2][2] += a.z * b.z; acc[2][3] += a.z * b.w;
            acc[3][0] += a.w * b.x; acc[3][1] += a.w * b.y;
            acc[3][2] += a.w * b.z; acc[3][3] += a.w * b.w;
        }
    }

#pragma unroll
    for (int rr = 0; rr < 4; rr++) {
        int row = base + i * 4 + rr;
        if (row < n) {
            float4 o = make_float4(acc[rr][0], acc[rr][1], acc[rr][2], acc[rr][3]);
            *(float4*)(H + (size_t)row * 64 + j * 4) = o;
            float ps = acc[rr][0] * atts[j * 4] + acc[rr][1] * atts[j * 4 + 1]
                     + acc[rr][2] * atts[j * 4 + 2] + acc[rr][3] * atts[j * 4 + 3];
            float pd = acc[rr][0] * attd[j * 4] + acc[rr][1] * attd[j * 4 + 1]
                     + acc[rr][2] * attd[j * 4 + 2] + acc[rr][3] * attd[j * 4 + 3];
            atomicAdd(&asd[i * 4 + rr], ps);
            atomicAdd(&asd[64 + i * 4 + rr], pd);
        }
    }
    __syncthreads();
    if (tid < 64 && base + tid < n) {
        AS[base + tid] = asd[tid];
        AD[base + tid] = asd[64 + tid];
    }
}

// ---------------- zero layer-1 accumulators ----------------------------------
__global__ void k_zeroacc(int n) {
    int total = n * 16;   // float4 count
    float4 z = make_float4(0.f, 0.f, 0.f, 0.f);
    for (int i = blockIdx.x * blockDim.x + threadIdx.x; i < total;
         i += gridDim.x * blockDim.x) {
        ((float4*)g_acc)[i] = z;
        if (i < n) g_den[i] = 0.f;
    }
}

// ---------------- layer-1 scatter aggregation (f32) --------------------------
__device__ __forceinline__ void red_v4(float* p, float a, float b, float c, float d) {
    asm volatile("red.global.add.v4.f32 [%0], {%1, %2, %3, %4};"
                 :: "l"(p), "f"(a), "f"(b), "f"(c), "f"(d) : "memory");
}

__global__ void __launch_bounds__(256)
k_scatagg(const float* __restrict__ H, const float* __restrict__ AS,
          const float* __restrict__ AD, int n) {
    int src = (blockIdx.x * blockDim.x + threadIdx.x) >> 5;
    int lane = threadIdx.x & 31;
    if (src >= n) return;

    int q = lane & 15;
    int half = lane >> 4;
    float4 hv = *(const float4*)(H + (size_t)src * 64 + q * 4);
    float as_v = AS[src];
    int beg = g_rp[src], end = g_rp[src + 1];

    int j = beg;
    for (; j + 1 < end; j += 2) {
        int d = g_sd[j + half];
        float e = as_v + AD[d];
        e = (e > 0.f) ? e : 0.2f * e;
        float w = __expf(e);
        float* ap = g_acc + (size_t)d * 64 + q * 4;
        red_v4(ap, w * hv.x, w * hv.y, w * hv.z, w * hv.w);
        if (q == 0) atomicAdd(&g_den[d], w);
    }
    if (j < end && half == 0) {
        int d = g_sd[j];
        float e = as_v + AD[d];
        e = (e > 0.f) ? e : 0.2f * e;
        float w = __expf(e);
        float* ap = g_acc + (size_t)d * 64 + q * 4;
        red_v4(ap, w * hv.x, w * hv.y, w * hv.z, w * hv.w);
        if (q == 0) atomicAdd(&g_den[d], w);
    }
}

// ---------------- SGEMM2 (64->64) with fused normalize+bias+relu on input ----
__global__ void __launch_bounds__(256)
k_sgemm64f(const float* __restrict__ Wg, const float* __restrict__ b1,
           const float* __restrict__ att_s, const float* __restrict__ att_d,
           float* __restrict__ H, float* __restrict__ AS, float* __restrict__ AD,
           int n) {
    __shared__ float xs[64 * 64];
    __shared__ float ws[64 * 64];
    __shared__ float atts[64], attd[64], bs[64];
    __shared__ float asd[128];

    int tid = threadIdx.x;
    int i = tid >> 4, j = tid & 15;
    int base = blockIdx.x * 64;

    if (tid < 64) { atts[tid] = att_s[tid]; attd[tid] = att_d[tid]; bs[tid] = b1[tid]; }
    if (tid < 128) asd[tid] = 0.f;
    __syncthreads();

    // X tile from g_acc with fused normalize+bias+relu; transposed+swizzled
#pragma unroll
    for (int t = tid; t < 1024; t += 256) {
        int row = t >> 4, c4 = t & 15;
        int rc = base + row < n ? base + row : n - 1;
        float inv = 1.f / (g_den[rc] + 1e-16f);
        float4 v = *(const float4*)(g_acc + (size_t)rc * 64 + c4 * 4);
        int g0 = row >> 2, r3 = row & 3;
#pragma unroll
        for (int s = 0; s < 4; s++) {
            int k = c4 * 4 + s;
            float val = (s == 0) ? v.x : (s == 1) ? v.y : (s == 2) ? v.z : v.w;
            val = fmaxf(val * inv + bs[k], 0.f);
            xs[k * 64 + ((g0 ^ (k & 15)) << 2) + r3] = val;
        }
    }
#pragma unroll
    for (int t = tid; t < 1024; t += 256) {
        int k = t >> 4, c4 = t & 15;
        *(float4*)(ws + k * 64 + c4 * 4) =
            *(const float4*)(Wg + (size_t)k * 64 + c4 * 4);
    }
    __syncthreads();

    float acc[4][4];
#pragma unroll
    for (int r = 0; r < 4; r++)
#pragma unroll
        for (int c = 0; c < 4; c++) acc[r][c] = 0.f;

#pragma unroll 4
    for (int k = 0; k < 64; k++) {
        float4 a = *(const float4*)(xs + k * 64 + ((i ^ (k & 15)) << 2));
        float4 b = *(const float4*)(ws + k * 64 + j * 4);
        acc[0][0] += a.x * b.x; acc[0][1] += a.x * b.y;
        acc[0][2] += a.x * b.z; acc[0][3] += a.x * b.w;
        acc[1][0] += a.y * b.x; acc[1][1] += a.y * b.y;
        acc[1][2] += a.y * b.z; acc[1][3] += a.y * b.w;
        acc[2][0] += a.z * b.x; acc[2][1] += a.z * b.y;
        acc[2][2] += a.z * b.z; acc[2][3] += a.z * b.w;
        acc[3][0] += a.w * b.x; acc[3][1] += a.w * b.y;
        acc[3][2] += a.w * b.z; acc[3][3] += a.w * b.w;
    }

#pragma unroll
    for (int rr = 0; rr < 4; rr++) {
        int row = base + i * 4 + rr;
        if (row < n) {
            float4 o = make_float4(acc[rr][0], acc[rr][1], acc[rr][2], acc[rr][3]);
            *(float4*)(H + (size_t)row * 64 + j * 4) = o;
            float ps = acc[rr][0] * atts[j * 4] + acc[rr][1] * atts[j * 4 + 1]
                     + acc[rr][2] * atts[j * 4 + 2] + acc[rr][3] * atts[j * 4 + 3];
            float pd = acc[rr][0] * attd[j * 4] + acc[rr][1] * attd[j * 4 + 1]
                     + acc[rr][2] * attd[j * 4 + 2] + acc[rr][3] * attd[j * 4 + 3];
            atomicAdd(&asd[i * 4 + rr], ps);
            atomicAdd(&asd[64 + i * 4 + rr], pd);
        }
    }
    __syncthreads();
    if (tid < 64 && base + tid < n) {
        AS[base + tid] = asd[tid];
        AD[base + tid] = asd[64 + tid];
    }
}

// ---------------- zero den2 ---------------------------------------------------
__global__ void k_zeroden(int n) {
    int i = blockIdx.x * blockDim.x + threadIdx.x;
    if (i < n) g_den[i] = 0.f;
}

// ---------------- layer-2 denominators + edge weights (warp per SRC) ---------
__global__ void __launch_bounds__(256)
k_den2(const float* __restrict__ AS, const float* __restrict__ AD, int n) {
    int src = (blockIdx.x * blockDim.x + threadIdx.x) >> 5;
    int lane = threadIdx.x & 31;
    if (src >= n) return;
    float as_v = AS[src];
    int beg = g_rp[src], end = g_rp[src + 1];
    for (int j = beg + lane; j < end; j += 32) {
        int d = g_sd[j];
        float e = as_v + AD[d];
        e = (e > 0.f) ? e : 0.2f * e;
        float w = __expf(e);
        g_w[j] = w;
        atomicAdd(&g_den[d], w);
    }
}

// ---------------- layer-2 collapsed aggregation+pool: warp per SRC -----------
__global__ void __launch_bounds__(256)
k_coefpool(const float* __restrict__ H2, int n) {
    __shared__ float sm[8][64];
    int warp = threadIdx.x >> 5, lane = threadIdx.x & 31;
    int gw = blockIdx.x * 8 + warp;
    int stride = gridDim.x * 8;

    float acc0 = 0.f, acc1 = 0.f;
    for (int src = gw; src < n; src += stride) {
        int beg = g_rp[src], end = g_rp[src + 1];
        float a = 0.f;
        for (int j = beg + lane; j < end; j += 32)
            a += g_w[j] / (g_den[g_sd[j]] + 1e-16f);
#pragma unroll
        for (int o = 16; o; o >>= 1) a += __shfl_xor_sync(0xffffffffu, a, o);
        const float* hp = H2 + (size_t)src * 64;
        acc0 += a * hp[lane];
        acc1 += a * hp[lane + 32];
    }
    sm[warp][lane] = acc0;
    sm[warp][lane + 32] = acc1;
    __syncthreads();
    if (threadIdx.x < 64) {
        float v = 0.f;
#pragma unroll
        for (int w = 0; w < 8; w++) v += sm[w][threadIdx.x];
        g_pool[blockIdx.x * 64 + threadIdx.x] = v;
    }
}

// ---------------- final reduce + bias ----------------------------------------
__global__ void k_pool_b(const float* __restrict__ b2, float* __restrict__ out,
                         int n) {
    int col = threadIdx.x;   // 64 threads
    float acc = 0.f;
    for (int b = 0; b < POOLB; b++) acc += g_pool[b * 64 + col];
    out[col] = acc * (1.0f / (float)n) + b2[col];
}

// ---------------- launch ----------------------------------------------------
extern "C" void kernel_launch(void* const* d_in, const int* in_sizes, int n_in,
                              void* d_out, int out_size) {
    const float* x   = (const float*)d_in[0];
    const void*  ei  = d_in[1];
    const float* W1  = (const float*)d_in[3];
    const float* as1 = (const float*)d_in[4];
    const float* ad1 = (const float*)d_in[5];
    const float* b1  = (const float*)d_in[6];
    const float* W2  = (const float*)d_in[7];
    const float* as2 = (const float*)d_in[8];
    const float* ad2 = (const float*)d_in[9];
    const float* b2  = (const float*)d_in[10];
    float* out = (float*)d_out;

    int n  = in_sizes[0] / 128;   // N nodes
    int E  = in_sizes[1] / 2;     // edges
    int EN = E + n;               // edges + self loops

    int sgemmBlocks = (n + 63) / 64;
    int aggBlocks   = (n + 7) / 8;

    k_zero<<<(n + 255) / 256, 256>>>(n);                               // 0
    int nq = E < 2048 ? E : 2048;
    k_detect<<<(nq + 255) / 256, 256>>>((const long long*)ei, nq);     // 1
    k_hist<<<(EN + 255) / 256, 256>>>(ei, E, EN, n);                   // 2
    k_sgemm128<<<sgemmBlocks, 256>>>(x, W1, as1, ad1,
                                     g_h1, g_as1, g_ad1, n);           // 3 <- profiled
    int nb = (n + 1023) / 1024;
    k_scan_block<<<nb, 1024>>>(n);
    k_scan_top<<<1, 128>>>(nb);
    k_scan_add<<<(n + 255) / 256, 256>>>(n, EN);
    k_scatter<<<(EN + 255) / 256, 256>>>(ei, E, EN, n);

    // --- layer 1: f32 scatter aggregation ---
    k_zeroacc<<<480, 256>>>(n);
    k_scatagg<<<aggBlocks, 256>>>(g_h1, g_as1, g_ad1, n);

    // --- layer 2: fused-norm SGEMM; collapsed aggregation+pool ---
    k_sgemm64f<<<sgemmBlocks, 256>>>(W2, b1, as2, ad2, g_h2, g_as2, g_ad2, n);
    k_zeroden<<<(n + 255) / 256, 256>>>(n);
    k_den2<<<aggBlocks, 256>>>(g_as2, g_ad2, n);
    k_coefpool<<<POOLB, 256>>>(g_h2, n);
    k_pool_b<<<1, 64>>>(b2, out, n);
}

// round 13
// speedup vs baseline: 2.3674x; 1.2920x over previous
#include <cuda_runtime.h>
#include <cuda_fp16.h>
#include <cstdint>

// ---------------- problem-size scratch (static device globals; no allocs) ---
#define NMAX 100096
#define EMAX 1600256
#define ENMAX (NMAX + EMAX)
#define POOLB 592

__device__ int    g_not64;               // 1 if edge_index is int32
__device__ int    g_deg[NMAX];
__device__ int    g_rp[NMAX + 1];        // CSR row pointers (by SRC)
__device__ int    g_cur[NMAX];
__device__ int    g_bsum[128];
__device__ int    g_sd[ENMAX];           // dst per CSR slot (src-sorted)
__device__ float  g_w[ENMAX];            // layer2 edge weights
__device__ float  g_u1[128], g_v1[128];  // W1 @ att_src1 / att_dst1
__device__ float  g_h2[NMAX * 64];       // layer2 features, row-major
__device__ float  g_as1[NMAX], g_ad1[NMAX];
__device__ float  g_as2[NMAX], g_ad2[NMAX];
__device__ float  g_acc[NMAX * 64];      // layer1 scatter accumulator
__device__ float  g_den[NMAX];           // denominators (layer1, then reused layer2)
__device__ float  g_pool[POOLB * 64];    // pool partials

// ---------------- init ------------------------------------------------------
__global__ void k_zero(int n) {
    int i = blockIdx.x * blockDim.x + threadIdx.x;
    if (i < n) g_deg[i] = 0;
    if (i == 0) g_not64 = 0;
}

// ---------------- edge-index dtype detection --------------------------------
__global__ void k_detect(const long long* __restrict__ ei, int nq) {
    int i = blockIdx.x * blockDim.x + threadIdx.x;
    if (i < nq && ((unsigned long long)ei[i] >> 32) != 0ull) atomicOr(&g_not64, 1);
}

__device__ __forceinline__ int load_idx(const void* ei, long long pos) {
    if (g_not64) return ((const int*)ei)[pos];
    return (int)((const long long*)ei)[pos];
}

__device__ __forceinline__ int clampi(int v, int n) {
    v = v < 0 ? 0 : v;
    return v >= n ? n - 1 : v;
}

// ---------------- u1 = W1 @ att_s, v1 = W1 @ att_d (1 block, 128 thr) --------
__global__ void k_wv(const float* __restrict__ Wg, const float* __restrict__ att_s,
                     const float* __restrict__ att_d) {
    __shared__ float as_[64], ad_[64];
    int t = threadIdx.x;
    if (t < 64) { as_[t] = att_s[t]; ad_[t] = att_d[t]; }
    __syncthreads();
    float u = 0.f, v = 0.f;
    const float* wr = Wg + (size_t)t * 64;
#pragma unroll 16
    for (int c = 0; c < 64; c++) { float w = wr[c]; u += w * as_[c]; v += w * ad_[c]; }
    g_u1[t] = u;
    g_v1[t] = v;
}

// ---------------- AS1/AD1 = X . u1 / X . v1 (warp per row, 4 rows/warp) ------
__global__ void __launch_bounds__(256)
k_mv1(const float* __restrict__ X, float* __restrict__ AS, float* __restrict__ AD,
      int n) {
    __shared__ float4 us[32], vs[32];
    int tid = threadIdx.x;
    if (tid < 32) { us[tid] = ((const float4*)g_u1)[tid]; vs[tid] = ((const float4*)g_v1)[tid]; }
    __syncthreads();
    int warp = tid >> 5, lane = tid & 31;
    int r0 = (blockIdx.x * 8 + warp) * 4;
    if (r0 >= n) return;

    float4 xv[4];
#pragma unroll
    for (int rr = 0; rr < 4; rr++) {
        int row = r0 + rr < n ? r0 + rr : n - 1;
        xv[rr] = ((const float4*)(X + (size_t)row * 128))[lane];
    }
    float4 u = us[lane], v = vs[lane];
#pragma unroll
    for (int rr = 0; rr < 4; rr++) {
        float ps = xv[rr].x * u.x + xv[rr].y * u.y + xv[rr].z * u.z + xv[rr].w * u.w;
        float pd = xv[rr].x * v.x + xv[rr].y * v.y + xv[rr].z * v.z + xv[rr].w * v.w;
#pragma unroll
        for (int o = 16; o; o >>= 1) {
            ps += __shfl_xor_sync(0xffffffffu, ps, o);
            pd += __shfl_xor_sync(0xffffffffu, pd, o);
        }
        if (lane == 0 && r0 + rr < n) { AS[r0 + rr] = ps; AD[r0 + rr] = pd; }
    }
}

// ---------------- out-degree histogram (by SRC, incl. self loops) ------------
__global__ void k_hist(const void* __restrict__ ei, int E, int EN, int n) {
    int i = blockIdx.x * blockDim.x + threadIdx.x;
    if (i >= EN) return;
    int s = (i < E) ? clampi(load_idx(ei, i), n) : (i - E);
    atomicAdd(&g_deg[s], 1);
}

// ---------------- prefix scan -------------------------------------------------
__global__ void k_scan_block(int n) {
    __shared__ int s[1024];
    int i = blockIdx.x * 1024 + threadIdx.x;
    int v = (i < n) ? g_deg[i] : 0;
    s[threadIdx.x] = v;
    __syncthreads();
#pragma unroll
    for (int o = 1; o < 1024; o <<= 1) {
        int t = (threadIdx.x >= (unsigned)o) ? s[threadIdx.x - o] : 0;
        __syncthreads();
        s[threadIdx.x] += t;
        __syncthreads();
    }
    if (i < n) g_rp[i] = s[threadIdx.x] - v;
    if (threadIdx.x == 1023) g_bsum[blockIdx.x] = s[1023];
}

__global__ void k_scan_top(int nb) {
    __shared__ int s[128];
    int t = threadIdx.x;
    int v = (t < nb) ? g_bsum[t] : 0;
    s[t] = v;
    __syncthreads();
#pragma unroll
    for (int o = 1; o < 128; o <<= 1) {
        int tv = (t >= (unsigned)o) ? s[t - o] : 0;
        __syncthreads();
        s[t] += tv;
        __syncthreads();
    }
    if (t < nb) g_bsum[t] = s[t] - v;
}

__global__ void k_scan_add(int n, int total) {
    int i = blockIdx.x * blockDim.x + threadIdx.x;
    if (i < n) {
        int v = g_rp[i] + g_bsum[i >> 10];
        g_rp[i] = v;
        g_cur[i] = v;
    }
    if (i == 0) g_rp[n] = total;
}

// ---------------- scatter edges into src-CSR order (store dst) --------------
__global__ void k_scatter(const void* __restrict__ ei, int E, int EN, int n) {
    int i = blockIdx.x * blockDim.x + threadIdx.x;
    if (i >= EN) return;
    int s, d;
    if (i < E) {
        s = clampi(load_idx(ei, i), n);
        d = clampi(load_idx(ei, (long long)E + i), n);
    } else { s = i - E; d = s; }
    int pos = atomicAdd(&g_cur[s], 1);
    if (pos >= 0 && pos < ENMAX) g_sd[pos] = d;
}

// ---------------- zero layer-1 accumulators ----------------------------------
__global__ void k_zeroacc(int n) {
    int total = n * 16;   // float4 count
    float4 z = make_float4(0.f, 0.f, 0.f, 0.f);
    for (int i = blockIdx.x * blockDim.x + threadIdx.x; i < total;
         i += gridDim.x * blockDim.x) {
        ((float4*)g_acc)[i] = z;
        if (i < n) g_den[i] = 0.f;
    }
}

// ---------------- red helper --------------------------------------------------
__device__ __forceinline__ void red_v4(float* p, float a, float b, float c, float d) {
    asm volatile("red.global.add.v4.f32 [%0], {%1, %2, %3, %4};"
                 :: "l"(p), "f"(a), "f"(b), "f"(c), "f"(d) : "memory");
}

// ---------------- SGEMM1 (128->64) with FUSED softmax scatter ----------------
// 64x64 tile, 4x4 micro-tiles; epilogue stages the h-tile in smem and scatters
// w*h into g_acc (AS/AD precomputed by k_mv1). No H1 array at all.
__global__ void __launch_bounds__(256)
k_sgemm128s(const float* __restrict__ X, const float* __restrict__ Wg,
            const float* __restrict__ AS, const float* __restrict__ AD, int n) {
    __shared__ float xs[64 * 68];   // staging (stride 64 + XOR) then out tile (stride 68)
    __shared__ float ws[64 * 64];
    __shared__ float sAS[64];
    __shared__ int   srp[65];

    int tid = threadIdx.x;
    int i = tid >> 4, j = tid & 15;
    int base = blockIdx.x * 64;

    if (tid < 64) sAS[tid] = AS[base + tid < n ? base + tid : n - 1];
    if (tid < 65) srp[tid] = g_rp[base + tid < n ? base + tid : n];

    float acc[4][4];
#pragma unroll
    for (int r = 0; r < 4; r++)
#pragma unroll
        for (int c = 0; c < 4; c++) acc[r][c] = 0.f;

#pragma unroll
    for (int ph = 0; ph < 2; ph++) {
        __syncthreads();
#pragma unroll
        for (int t = tid; t < 1024; t += 256) {
            int row = t >> 4, c4 = t & 15;
            int rc = base + row < n ? base + row : n - 1;
            float4 v = *(const float4*)(X + (size_t)rc * 128 + ph * 64 + c4 * 4);
            int g0 = row >> 2, r3 = row & 3;
#pragma unroll
            for (int s = 0; s < 4; s++) {
                int k = c4 * 4 + s;
                float val = (s == 0) ? v.x : (s == 1) ? v.y : (s == 2) ? v.z : v.w;
                xs[k * 64 + ((g0 ^ (k & 15)) << 2) + r3] = val;
            }
        }
#pragma unroll
        for (int t = tid; t < 1024; t += 256) {
            int k = t >> 4, c4 = t & 15;
            *(float4*)(ws + k * 64 + c4 * 4) =
                *(const float4*)(Wg + (size_t)(ph * 64 + k) * 64 + c4 * 4);
        }
        __syncthreads();

#pragma unroll 4
        for (int k = 0; k < 64; k++) {
            float4 a = *(const float4*)(xs + k * 64 + ((i ^ (k & 15)) << 2));
            float4 b = *(const float4*)(ws + k * 64 + j * 4);
            acc[0][0] += a.x * b.x; acc[0][1] += a.x * b.y;
            acc[0][2] += a.x * b.z; acc[0][3] += a.x * b.w;
            acc[1][0] += a.y * b.x; acc[1][1] += a.y * b.y;
            acc[1][2] += a.y * b.z; acc[1][3] += a.y * b.w;
            acc[2][0] += a.z * b.x; acc[2][1] += a.z * b.y;
            acc[2][2] += a.z * b.z; acc[2][3] += a.z * b.w;
            acc[3][0] += a.w * b.x; acc[3][1] += a.w * b.y;
            acc[3][2] += a.w * b.z; acc[3][3] += a.w * b.w;
        }
    }

    // ---- epilogue: stage out tile row-major (stride 68), then scatter ----
    __syncthreads();
#pragma unroll
    for (int rr = 0; rr < 4; rr++)
        *(float4*)(xs + (i * 4 + rr) * 68 + j * 4) =
            make_float4(acc[rr][0], acc[rr][1], acc[rr][2], acc[rr][3]);
    __syncthreads();

    int warp = tid >> 5, lane = tid & 31;
    int q = lane & 15, half = lane >> 4;
    for (int lr = warp * 8; lr < warp * 8 + 8; lr++) {
        int beg = srp[lr], end = srp[lr + 1];
        if (beg >= end) continue;
        float4 hv = *(const float4*)(xs + lr * 68 + q * 4);
        float as_v = sAS[lr];
        int jj = beg;
        for (; jj + 1 < end; jj += 2) {
            int d = g_sd[jj + half];
            float e = as_v + AD[d];
            e = (e > 0.f) ? e : 0.2f * e;
            float w = __expf(e);
            float* ap = g_acc + (size_t)d * 64 + q * 4;
            red_v4(ap, w * hv.x, w * hv.y, w * hv.z, w * hv.w);
            if (q == 0) atomicAdd(&g_den[d], w);
        }
        if (jj < end && half == 0) {
            int d = g_sd[jj];
            float e = as_v + AD[d];
            e = (e > 0.f) ? e : 0.2f * e;
            float w = __expf(e);
            float* ap = g_acc + (size_t)d * 64 + q * 4;
            red_v4(ap, w * hv.x, w * hv.y, w * hv.z, w * hv.w);
            if (q == 0) atomicAdd(&g_den[d], w);
        }
    }
}

// ---------------- SGEMM2 (64->64) with fused normalize+bias+relu on input ----
__global__ void __launch_bounds__(256)
k_sgemm64f(const float* __restrict__ Wg, const float* __restrict__ b1,
           const float* __restrict__ att_s, const float* __restrict__ att_d,
           float* __restrict__ H, float* __restrict__ AS, float* __restrict__ AD,
           int n) {
    __shared__ float xs[64 * 64];
    __shared__ float ws[64 * 64];
    __shared__ float atts[64], attd[64], bs[64];
    __shared__ float asd[128];

    int tid = threadIdx.x;
    int i = tid >> 4, j = tid & 15;
    int base = blockIdx.x * 64;

    if (tid < 64) { atts[tid] = att_s[tid]; attd[tid] = att_d[tid]; bs[tid] = b1[tid]; }
    if (tid < 128) asd[tid] = 0.f;
    __syncthreads();

#pragma unroll
    for (int t = tid; t < 1024; t += 256) {
        int row = t >> 4, c4 = t & 15;
        int rc = base + row < n ? base + row : n - 1;
        float inv = 1.f / (g_den[rc] + 1e-16f);
        float4 v = *(const float4*)(g_acc + (size_t)rc * 64 + c4 * 4);
        int g0 = row >> 2, r3 = row & 3;
#pragma unroll
        for (int s = 0; s < 4; s++) {
            int k = c4 * 4 + s;
            float val = (s == 0) ? v.x : (s == 1) ? v.y : (s == 2) ? v.z : v.w;
            val = fmaxf(val * inv + bs[k], 0.f);
            xs[k * 64 + ((g0 ^ (k & 15)) << 2) + r3] = val;
        }
    }
#pragma unroll
    for (int t = tid; t < 1024; t += 256) {
        int k = t >> 4, c4 = t & 15;
        *(float4*)(ws + k * 64 + c4 * 4) =
            *(const float4*)(Wg + (size_t)k * 64 + c4 * 4);
    }
    __syncthreads();

    float acc[4][4];
#pragma unroll
    for (int r = 0; r < 4; r++)
#pragma unroll
        for (int c = 0; c < 4; c++) acc[r][c] = 0.f;

#pragma unroll 4
    for (int k = 0; k < 64; k++) {
        float4 a = *(const float4*)(xs + k * 64 + ((i ^ (k & 15)) << 2));
        float4 b = *(const float4*)(ws + k * 64 + j * 4);
        acc[0][0] += a.x * b.x; acc[0][1] += a.x * b.y;
        acc[0][2] += a.x * b.z; acc[0][3] += a.x * b.w;
        acc[1][0] += a.y * b.x; acc[1][1] += a.y * b.y;
        acc[1][2] += a.y * b.z; acc[1][3] += a.y * b.w;
        acc[2][0] += a.z * b.x; acc[2][1] += a.z * b.y;
        acc[2][2] += a.z * b.z; acc[2][3] += a.z * b.w;
        acc[3][0] += a.w * b.x; acc[3][1] += a.w * b.y;
        acc[3][2] += a.w * b.z; acc[3][3] += a.w * b.w;
    }

#pragma unroll
    for (int rr = 0; rr < 4; rr++) {
        int row = base + i * 4 + rr;
        if (row < n) {
            float4 o = make_float4(acc[rr][0], acc[rr][1], acc[rr][2], acc[rr][3]);
            *(float4*)(H + (size_t)row * 64 + j * 4) = o;
            float ps = acc[rr][0] * atts[j * 4] + acc[rr][1] * atts[j * 4 + 1]
                     + acc[rr][2] * atts[j * 4 + 2] + acc[rr][3] * atts[j * 4 + 3];
            float pd = acc[rr][0] * attd[j * 4] + acc[rr][1] * attd[j * 4 + 1]
                     + acc[rr][2] * attd[j * 4 + 2] + acc[rr][3] * attd[j * 4 + 3];
            atomicAdd(&asd[i * 4 + rr], ps);
            atomicAdd(&asd[64 + i * 4 + rr], pd);
        }
    }
    __syncthreads();
    if (tid < 64 && base + tid < n) {
        AS[base + tid] = asd[tid];
        AD[base + tid] = asd[64 + tid];
    }
}

// ---------------- zero den2 ---------------------------------------------------
__global__ void k_zeroden(int n) {
    int i = blockIdx.x * blockDim.x + threadIdx.x;
    if (i < n) g_den[i] = 0.f;
}

// ---------------- layer-2 denominators + edge weights (warp per SRC) ---------
__global__ void __launch_bounds__(256)
k_den2(const float* __restrict__ AS, const float* __restrict__ AD, int n) {
    int src = (blockIdx.x * blockDim.x + threadIdx.x) >> 5;
    int lane = threadIdx.x & 31;
    if (src >= n) return;
    float as_v = AS[src];
    int beg = g_rp[src], end = g_rp[src + 1];
    for (int j = beg + lane; j < end; j += 32) {
        int d = g_sd[j];
        float e = as_v + AD[d];
        e = (e > 0.f) ? e : 0.2f * e;
        float w = __expf(e);
        g_w[j] = w;
        atomicAdd(&g_den[d], w);
    }
}

// ---------------- layer-2 collapsed aggregation+pool: warp per SRC -----------
__global__ void __launch_bounds__(256)
k_coefpool(const float* __restrict__ H2, int n) {
    __shared__ float sm[8][64];
    int warp = threadIdx.x >> 5, lane = threadIdx.x & 31;
    int gw = blockIdx.x * 8 + warp;
    int stride = gridDim.x * 8;

    float acc0 = 0.f, acc1 = 0.f;
    for (int src = gw; src < n; src += stride) {
        int beg = g_rp[src], end = g_rp[src + 1];
        float a = 0.f;
        for (int j = beg + lane; j < end; j += 32)
            a += g_w[j] / (g_den[g_sd[j]] + 1e-16f);
#pragma unroll
        for (int o = 16; o; o >>= 1) a += __shfl_xor_sync(0xffffffffu, a, o);
        const float* hp = H2 + (size_t)src * 64;
        acc0 += a * hp[lane];
        acc1 += a * hp[lane + 32];
    }
    sm[warp][lane] = acc0;
    sm[warp][lane + 32] = acc1;
    __syncthreads();
    if (threadIdx.x < 64) {
        float v = 0.f;
#pragma unroll
        for (int w = 0; w < 8; w++) v += sm[w][threadIdx.x];
        g_pool[blockIdx.x * 64 + threadIdx.x] = v;
    }
}

// ---------------- final reduce + bias ----------------------------------------
__global__ void k_pool_b(const float* __restrict__ b2, float* __restrict__ out,
                         int n) {
    int col = threadIdx.x;   // 64 threads
    float acc = 0.f;
    for (int b = 0; b < POOLB; b++) acc += g_pool[b * 64 + col];
    out[col] = acc * (1.0f / (float)n) + b2[col];
}

// ---------------- launch ----------------------------------------------------
extern "C" void kernel_launch(void* const* d_in, const int* in_sizes, int n_in,
                              void* d_out, int out_size) {
    const float* x   = (const float*)d_in[0];
    const void*  ei  = d_in[1];
    const float* W1  = (const float*)d_in[3];
    const float* as1 = (const float*)d_in[4];
    const float* ad1 = (const float*)d_in[5];
    const float* b1  = (const float*)d_in[6];
    const float* W2  = (const float*)d_in[7];
    const float* as2 = (const float*)d_in[8];
    const float* ad2 = (const float*)d_in[9];
    const float* b2  = (const float*)d_in[10];
    float* out = (float*)d_out;

    int n  = in_sizes[0] / 128;   // N nodes
    int E  = in_sizes[1] / 2;     // edges
    int EN = E + n;               // edges + self loops

    int sgemmBlocks = (n + 63) / 64;
    int aggBlocks   = (n + 7) / 8;

    k_zero<<<(n + 255) / 256, 256>>>(n);                               // 0
    int nq = E < 2048 ? E : 2048;
    k_detect<<<(nq + 255) / 256, 256>>>((const long long*)ei, nq);     // 1
    k_wv<<<1, 128>>>(W1, as1, ad1);                                    // 2
    k_mv1<<<(n + 31) / 32, 256>>>(x, g_as1, g_ad1, n);                 // 3 <- profiled (X stream)
    k_hist<<<(EN + 255) / 256, 256>>>(ei, E, EN, n);                   // 4
    int nb = (n + 1023) / 1024;
    k_scan_block<<<nb, 1024>>>(n);
    k_scan_top<<<1, 128>>>(nb);
    k_scan_add<<<(n + 255) / 256, 256>>>(n, EN);
    k_scatter<<<(EN + 255) / 256, 256>>>(ei, E, EN, n);
    k_zeroacc<<<480, 256>>>(n);

    // --- layer 1: GEMM with fused softmax scatter ---
    k_sgemm128s<<<sgemmBlocks, 256>>>(x, W1, g_as1, g_ad1, n);

    // --- layer 2: fused-norm SGEMM; collapsed aggregation+pool ---
    k_sgemm64f<<<sgemmBlocks, 256>>>(W2, b1, as2, ad2, g_h2, g_as2, g_ad2, n);
    k_zeroden<<<(n + 255) / 256, 256>>>(n);
    k_den2<<<aggBlocks, 256>>>(g_as2, g_ad2, n);
    k_coefpool<<<POOLB, 256>>>(g_h2, n);
    k_pool_b<<<1, 64>>>(b2, out, n);
}